// round 5
// baseline (speedup 1.0000x reference)
#include <cuda_runtime.h>
#include <cuda_bf16.h>

#define N_NODES 50000
#define E_EDGES 800000
#define K_TOT   256     // concat K (mean 128 | self 128) for every layer

// ---------------- device scratch (no allocs allowed) ----------------
__device__ int   g_deg[N_NODES];
__device__ int   g_rowptr[N_NODES + 1];
__device__ int   g_cursor[N_NODES];
__device__ int   g_col[E_EDGES];
__device__ __align__(16) float g_acat[(size_t)N_NODES * K_TOT];   // [N, 256] = [mean | h]
__device__ __align__(16) float g_h0[(size_t)N_NODES * 128];
__device__ __align__(16) float g_h1[(size_t)N_NODES * 128];
__device__ __align__(16) float g_B[K_TOT * 256];                  // [256, Do] combined weight

// ---------------- CSR build ----------------
__global__ void k_zero_deg() {
    int i = blockIdx.x * blockDim.x + threadIdx.x;
    if (i < N_NODES) g_deg[i] = 0;
}

__global__ void k_count(const int* __restrict__ ei) {
    int e = blockIdx.x * blockDim.x + threadIdx.x;
    if (e < E_EDGES) {
        int d = ei[E_EDGES + e];
        if (d >= 0 && d < N_NODES) atomicAdd(&g_deg[d], 1);
    }
}

// single-block exclusive scan over g_deg -> g_rowptr, also seeds g_cursor
__global__ void k_scan() {
    __shared__ int s[1024];
    __shared__ int run;
    int t = threadIdx.x;
    if (t == 0) run = 0;
    __syncthreads();
    for (int base = 0; base < N_NODES; base += 1024) {
        int v = (base + t < N_NODES) ? g_deg[base + t] : 0;
        s[t] = v;
        __syncthreads();
        for (int off = 1; off < 1024; off <<= 1) {
            int x = (t >= off) ? s[t - off] : 0;
            __syncthreads();
            s[t] += x;
            __syncthreads();
        }
        int excl = run + s[t] - v;
        if (base + t < N_NODES) { g_rowptr[base + t] = excl; g_cursor[base + t] = excl; }
        __syncthreads();
        if (t == 0) run += s[1023];
        __syncthreads();
    }
    if (t == 0) g_rowptr[N_NODES] = run;
}

__global__ void k_fill(const int* __restrict__ ei) {
    int e = blockIdx.x * blockDim.x + threadIdx.x;
    if (e < E_EDGES) {
        int s = ei[e];
        int d = ei[E_EDGES + e];
        if (d >= 0 && d < N_NODES && s >= 0 && s < N_NODES) {
            int p = atomicAdd(&g_cursor[d], 1);
            g_col[p] = s;
        }
    }
}

// ---------------- combined weight prep: g_B[k][j] = k<128 ? Wl[j][k] : Wr[j][k-128]
__global__ void k_prep_w(const float* __restrict__ Wl, const float* __restrict__ Wr, int Do) {
    int idx = blockIdx.x * blockDim.x + threadIdx.x;
    if (idx < K_TOT * Do) {
        int k = idx / Do, j = idx % Do;
        g_B[idx] = (k < 128) ? Wl[j * 128 + k] : Wr[j * 128 + (k - 128)];
    }
}

// ---------------- aggregation: one warp per node, gather + mean, write [mean|x] to g_acat
__global__ void k_agg(const float* __restrict__ x_ext, int sel) {
    const float* xin = (sel == 0) ? x_ext : (sel == 1) ? g_h0 : g_h1;
    int node = blockIdx.x * (blockDim.x >> 5) + (threadIdx.x >> 5);
    int lane = threadIdx.x & 31;
    if (node >= N_NODES) return;
    int beg = g_rowptr[node], end = g_rowptr[node + 1];
    const float4* x4 = (const float4*)xin;

    float4 a0 = {0.f, 0.f, 0.f, 0.f};
    float4 a1 = {0.f, 0.f, 0.f, 0.f};
    int e = beg;
    for (; e + 1 < end; e += 2) {
        int s0 = g_col[e], s1 = g_col[e + 1];
        float4 v0 = x4[(size_t)s0 * 32 + lane];
        float4 v1 = x4[(size_t)s1 * 32 + lane];
        a0.x += v0.x; a0.y += v0.y; a0.z += v0.z; a0.w += v0.w;
        a1.x += v1.x; a1.y += v1.y; a1.z += v1.z; a1.w += v1.w;
    }
    if (e < end) {
        int s0 = g_col[e];
        float4 v0 = x4[(size_t)s0 * 32 + lane];
        a0.x += v0.x; a0.y += v0.y; a0.z += v0.z; a0.w += v0.w;
    }
    int cnt = end - beg;
    float inv = 1.0f / (float)(cnt > 0 ? cnt : 1);
    float4 m;
    m.x = (a0.x + a1.x) * inv;
    m.y = (a0.y + a1.y) * inv;
    m.z = (a0.z + a1.z) * inv;
    m.w = (a0.w + a1.w) * inv;

    float4* A = (float4*)g_acat;
    A[(size_t)node * 64 + lane]      = m;                               // cols 0..127: mean
    A[(size_t)node * 64 + 32 + lane] = x4[(size_t)node * 32 + lane];    // cols 128..255: self
}

// ---------------- fused SGEMM: C[N,Do] = g_acat[N,256] @ g_B[256,Do] + bias (+relu)
// BM=128, BN=64, BK=16, 256 threads, 8x4 microtile
__global__ __launch_bounds__(256) void k_gemm(const float* __restrict__ bias,
                                              float* __restrict__ out_ext,
                                              int Do, int relu, int csel) {
    const int BM = 128, BN = 64, BK = 16;
    float* C = (csel == 0) ? g_h0 : (csel == 1) ? g_h1 : out_ext;

    __shared__ float As[BK][BM + 4];
    __shared__ float Bs[BK][BN];

    int t = threadIdx.x;
    int block_m = blockIdx.y * BM;
    int block_n = blockIdx.x * BN;
    int ty = t >> 4;      // 0..15
    int tx = t & 15;      // 0..15

    float acc[8][4];
    #pragma unroll
    for (int i = 0; i < 8; i++)
        #pragma unroll
        for (int j = 0; j < 4; j++) acc[i][j] = 0.f;

    for (int k0 = 0; k0 < K_TOT; k0 += BK) {
        // load A tile: 512 float4, 2 per thread
        #pragma unroll
        for (int i = 0; i < 2; i++) {
            int idx = t + i * 256;
            int m = idx >> 2;      // 0..127
            int kq = idx & 3;      // 0..3 (float4 within BK)
            int row = block_m + m;
            float4 v = {0.f, 0.f, 0.f, 0.f};
            if (row < N_NODES)
                v = *(const float4*)&g_acat[(size_t)row * K_TOT + k0 + kq * 4];
            As[kq * 4 + 0][m] = v.x;
            As[kq * 4 + 1][m] = v.y;
            As[kq * 4 + 2][m] = v.z;
            As[kq * 4 + 3][m] = v.w;
        }
        // load B tile: 256 float4, 1 per thread
        {
            int kr = t >> 4;       // 0..15
            int c4 = t & 15;       // 0..15
            float4 v = *(const float4*)&g_B[(size_t)(k0 + kr) * Do + block_n + c4 * 4];
            *(float4*)&Bs[kr][c4 * 4] = v;
        }
        __syncthreads();

        #pragma unroll
        for (int k = 0; k < BK; k++) {
            float4 b4 = *(float4*)&Bs[k][tx * 4];
            float a[8];
            #pragma unroll
            for (int i = 0; i < 8; i++) a[i] = As[k][ty * 8 + i];
            #pragma unroll
            for (int i = 0; i < 8; i++) {
                acc[i][0] += a[i] * b4.x;
                acc[i][1] += a[i] * b4.y;
                acc[i][2] += a[i] * b4.z;
                acc[i][3] += a[i] * b4.w;
            }
        }
        __syncthreads();
    }

    float4 bb = *(const float4*)&bias[block_n + tx * 4];
    #pragma unroll
    for (int i = 0; i < 8; i++) {
        int row = block_m + ty * 8 + i;
        if (row < N_NODES) {
            float4 o;
            o.x = acc[i][0] + bb.x;
            o.y = acc[i][1] + bb.y;
            o.z = acc[i][2] + bb.z;
            o.w = acc[i][3] + bb.w;
            if (relu) {
                o.x = fmaxf(o.x, 0.f); o.y = fmaxf(o.y, 0.f);
                o.z = fmaxf(o.z, 0.f); o.w = fmaxf(o.w, 0.f);
            }
            *(float4*)&C[(size_t)row * Do + block_n + tx * 4] = o;
        }
    }
}

extern "C" void kernel_launch(void* const* d_in, const int* in_sizes, int n_in,
                              void* d_out, int out_size) {
    const float* x   = (const float*)d_in[0];
    const int*   ei  = (const int*)d_in[1];     // int32! (harness converts int64)
    const float* Wl0 = (const float*)d_in[2];
    const float* bl0 = (const float*)d_in[3];
    const float* Wr0 = (const float*)d_in[4];
    const float* Wl1 = (const float*)d_in[5];
    const float* bl1 = (const float*)d_in[6];
    const float* Wr1 = (const float*)d_in[7];
    const float* Wl2 = (const float*)d_in[8];
    const float* bl2 = (const float*)d_in[9];
    const float* Wr2 = (const float*)d_in[10];
    float* out = (float*)d_out;

    // --- CSR build (once, reused by all 3 layers) ---
    k_zero_deg<<<(N_NODES + 255) / 256, 256>>>();
    k_count<<<(E_EDGES + 255) / 256, 256>>>(ei);
    k_scan<<<1, 1024>>>();
    k_fill<<<(E_EDGES + 255) / 256, 256>>>(ei);

    dim3 gemm_block(256);
    int  grid_m = (N_NODES + 127) / 128;

    // --- layer 0: x -> g_h0 (relu) ---
    k_prep_w<<<(K_TOT * 128 + 255) / 256, 256>>>(Wl0, Wr0, 128);
    k_agg<<<(N_NODES + 7) / 8, 256>>>(x, 0);
    k_gemm<<<dim3(128 / 64, grid_m), gemm_block>>>(bl0, nullptr, 128, 1, 0);

    // --- layer 1: g_h0 -> g_h1 (relu) ---
    k_prep_w<<<(K_TOT * 128 + 255) / 256, 256>>>(Wl1, Wr1, 128);
    k_agg<<<(N_NODES + 7) / 8, 256>>>(nullptr, 1);
    k_gemm<<<dim3(128 / 64, grid_m), gemm_block>>>(bl1, nullptr, 128, 1, 1);

    // --- layer 2: g_h1 -> out (no relu) ---
    k_prep_w<<<(K_TOT * 256 + 255) / 256, 256>>>(Wl2, Wr2, 256);
    k_agg<<<(N_NODES + 7) / 8, 256>>>(nullptr, 2);
    k_gemm<<<dim3(256 / 64, grid_m), gemm_block>>>(bl2, out, 256, 0, 2);
}

// round 10
// speedup vs baseline: 1.5701x; 1.5701x over previous
#include <cuda_runtime.h>
#include <cuda_bf16.h>
#include <cstdint>

#define N_NODES 50000
#define E_EDGES 800000
#define K_TOT   256     // concat K (mean 128 | self 128) for every layer

// ---------------- device scratch (no allocs allowed) ----------------
__device__ int   g_deg[N_NODES];
__device__ int   g_rowptr[N_NODES + 1];
__device__ int   g_cursor[N_NODES];
__device__ int   g_col[E_EDGES];
__device__ __align__(16) __nv_bfloat16 g_Ahi[(size_t)N_NODES * K_TOT];  // [N,256] hi split of [mean|h]
__device__ __align__(16) __nv_bfloat16 g_Alo[(size_t)N_NODES * K_TOT];  // [N,256] lo split
__device__ __align__(16) __nv_bfloat16 g_Bhi[256 * K_TOT];              // [Do,256] weight hi (K-major)
__device__ __align__(16) __nv_bfloat16 g_Blo[256 * K_TOT];              // [Do,256] weight lo
__device__ __align__(16) float g_h0[(size_t)N_NODES * 128];
__device__ __align__(16) float g_h1[(size_t)N_NODES * 128];

// ---------------- CSR build ----------------
__global__ void k_zero_deg() {
    int i = blockIdx.x * blockDim.x + threadIdx.x;
    if (i < N_NODES) g_deg[i] = 0;
}
__global__ void k_count(const int* __restrict__ ei) {
    int e = blockIdx.x * blockDim.x + threadIdx.x;
    if (e < E_EDGES) {
        int d = ei[E_EDGES + e];
        if (d >= 0 && d < N_NODES) atomicAdd(&g_deg[d], 1);
    }
}
__global__ void k_scan() {   // 1024 threads, shuffle-based block scan
    __shared__ int wsum[32];
    __shared__ int run_s;
    int t = threadIdx.x, lane = t & 31, wd = t >> 5;
    if (t == 0) run_s = 0;
    __syncthreads();
    for (int base = 0; base < N_NODES; base += 1024) {
        int i = base + t;
        int v = (i < N_NODES) ? g_deg[i] : 0;
        int s = v;
        #pragma unroll
        for (int o = 1; o < 32; o <<= 1) {
            int n = __shfl_up_sync(0xffffffffu, s, o);
            if (lane >= o) s += n;
        }
        if (lane == 31) wsum[wd] = s;
        __syncthreads();
        if (wd == 0) {
            int w = wsum[lane];
            #pragma unroll
            for (int o = 1; o < 32; o <<= 1) {
                int n = __shfl_up_sync(0xffffffffu, w, o);
                if (lane >= o) w += n;
            }
            wsum[lane] = w;
        }
        __syncthreads();
        int excl = run_s + (wd ? wsum[wd - 1] : 0) + s - v;
        if (i < N_NODES) { g_rowptr[i] = excl; g_cursor[i] = excl; }
        __syncthreads();
        if (t == 0) run_s += wsum[31];
        __syncthreads();
    }
    if (t == 0) g_rowptr[N_NODES] = run_s;
}
__global__ void k_fill(const int* __restrict__ ei) {
    int e = blockIdx.x * blockDim.x + threadIdx.x;
    if (e < E_EDGES) {
        int s = ei[e];
        int d = ei[E_EDGES + e];
        if (d >= 0 && d < N_NODES && s >= 0 && s < N_NODES) {
            int p = atomicAdd(&g_cursor[d], 1);
            g_col[p] = s;
        }
    }
}

// ---------------- weight prep: combined K-major [j][k], split hi/lo bf16 ----------------
__global__ void k_prep_w(const float* __restrict__ Wl, const float* __restrict__ Wr, int Do) {
    int idx = blockIdx.x * blockDim.x + threadIdx.x;
    if (idx < Do * K_TOT) {
        int j = idx >> 8, k = idx & 255;
        float v = (k < 128) ? Wl[j * 128 + k] : Wr[j * 128 + (k - 128)];
        __nv_bfloat16 hi = __float2bfloat16_rn(v);
        float lo = v - __bfloat162float(hi);
        g_Bhi[idx] = hi;
        g_Blo[idx] = __float2bfloat16_rn(lo);
    }
}

// ---------------- aggregation: warp/node gather-mean, emit hi/lo bf16 split ----------------
__device__ __forceinline__ void store_split(size_t off, float4 v) {
    __nv_bfloat16 h0 = __float2bfloat16_rn(v.x), h1 = __float2bfloat16_rn(v.y);
    __nv_bfloat16 h2 = __float2bfloat16_rn(v.z), h3 = __float2bfloat16_rn(v.w);
    __nv_bfloat162 a; a.x = h0; a.y = h1;
    __nv_bfloat162 b; b.x = h2; b.y = h3;
    *(__nv_bfloat162*)(g_Ahi + off)     = a;
    *(__nv_bfloat162*)(g_Ahi + off + 2) = b;
    __nv_bfloat162 la, lb;
    la.x = __float2bfloat16_rn(v.x - __bfloat162float(h0));
    la.y = __float2bfloat16_rn(v.y - __bfloat162float(h1));
    lb.x = __float2bfloat16_rn(v.z - __bfloat162float(h2));
    lb.y = __float2bfloat16_rn(v.w - __bfloat162float(h3));
    *(__nv_bfloat162*)(g_Alo + off)     = la;
    *(__nv_bfloat162*)(g_Alo + off + 2) = lb;
}

__global__ void k_agg(const float* __restrict__ x_ext, int sel) {
    const float* xin = (sel == 0) ? x_ext : (sel == 1) ? g_h0 : g_h1;
    int node = blockIdx.x * (blockDim.x >> 5) + (threadIdx.x >> 5);
    int lane = threadIdx.x & 31;
    if (node >= N_NODES) return;
    int beg = g_rowptr[node], end = g_rowptr[node + 1];
    const float4* x4 = (const float4*)xin;

    float4 a0 = {0.f, 0.f, 0.f, 0.f};
    float4 a1 = {0.f, 0.f, 0.f, 0.f};
    int e = beg;
    for (; e + 1 < end; e += 2) {
        int s0 = g_col[e], s1 = g_col[e + 1];
        float4 v0 = x4[(size_t)s0 * 32 + lane];
        float4 v1 = x4[(size_t)s1 * 32 + lane];
        a0.x += v0.x; a0.y += v0.y; a0.z += v0.z; a0.w += v0.w;
        a1.x += v1.x; a1.y += v1.y; a1.z += v1.z; a1.w += v1.w;
    }
    if (e < end) {
        int s0 = g_col[e];
        float4 v0 = x4[(size_t)s0 * 32 + lane];
        a0.x += v0.x; a0.y += v0.y; a0.z += v0.z; a0.w += v0.w;
    }
    int cnt = end - beg;
    float inv = 1.0f / (float)(cnt > 0 ? cnt : 1);
    float4 m;
    m.x = (a0.x + a1.x) * inv;
    m.y = (a0.y + a1.y) * inv;
    m.z = (a0.z + a1.z) * inv;
    m.w = (a0.w + a1.w) * inv;

    size_t base = (size_t)node * K_TOT + 4 * lane;
    store_split(base, m);                                   // cols 0..127: mean
    store_split(base + 128, x4[(size_t)node * 32 + lane]);  // cols 128..255: self
}

// ---------------- mma.sync bf16 helper ----------------
__device__ __forceinline__ void mma16816(float* c, uint32_t a0, uint32_t a1, uint32_t a2, uint32_t a3,
                                         uint32_t b0, uint32_t b1) {
    asm volatile("mma.sync.aligned.m16n8k16.row.col.f32.bf16.bf16.f32 "
                 "{%0,%1,%2,%3}, {%4,%5,%6,%7}, {%8,%9}, {%0,%1,%2,%3};"
                 : "+f"(c[0]), "+f"(c[1]), "+f"(c[2]), "+f"(c[3])
                 : "r"(a0), "r"(a1), "r"(a2), "r"(a3), "r"(b0), "r"(b1));
}

// ---------------- tensor-core GEMM: C[N,DO] = split([mean|h]) @ split(W)^T + bias (+relu)
// BM=128, BN=64, K chunks of 64. 8 warps: 4(M) x 2(N), warp tile 32x32.
// D += Ahi*Bhi + Ahi*Blo + Alo*Bhi  (fp32 accum in registers)
#define S_STRIDE 72   // bf16 elems per SMEM row (144B: 16B-aligned, conflict-free frags)
template<int DO, bool RELU>
__global__ __launch_bounds__(256) void k_gemm_mma(const float* __restrict__ bias,
                                                  float* __restrict__ Cext, int csel) {
    extern __shared__ __nv_bfloat16 sm[];
    __nv_bfloat16* As_hi = sm;                        // [128][72]
    __nv_bfloat16* As_lo = sm + 128 * S_STRIDE;       // [128][72]
    __nv_bfloat16* Bs_hi = sm + 256 * S_STRIDE;       // [64][72]
    __nv_bfloat16* Bs_lo = sm + 320 * S_STRIDE;       // [64][72]

    float* C = (csel == 0) ? g_h0 : (csel == 1) ? g_h1 : Cext;
    const int tid = threadIdx.x;
    const int wid = tid >> 5, lane = tid & 31;
    const int warp_m = wid & 3, warp_n = wid >> 2;    // 4 x 2
    const int g = lane >> 2, tg = lane & 3;           // mma fragment coords
    const int block_m = blockIdx.x * 128;
    const int block_n = blockIdx.y * 64;

    float acc[2][4][4];
    #pragma unroll
    for (int mi = 0; mi < 2; mi++)
        #pragma unroll
        for (int ni = 0; ni < 4; ni++)
            #pragma unroll
            for (int j = 0; j < 4; j++) acc[mi][ni][j] = 0.f;

    for (int ch = 0; ch < 4; ch++) {
        const int k0g = ch * 64;     // global k offset of this chunk
        // stage A: 128 rows x 64 cols (8 uint4/row), hi + lo
        #pragma unroll
        for (int it = 0; it < 4; it++) {
            int idx = tid + it * 256;          // 0..1023
            int r = idx >> 3, c8 = idx & 7;
            int row = block_m + r;
            uint4 vh = {0, 0, 0, 0}, vl = {0, 0, 0, 0};
            if (row < N_NODES) {
                size_t gi = (size_t)row * (K_TOT / 8) + (k0g >> 3) + c8;
                vh = ((const uint4*)g_Ahi)[gi];
                vl = ((const uint4*)g_Alo)[gi];
            }
            *(uint4*)(As_hi + r * S_STRIDE + c8 * 8) = vh;
            *(uint4*)(As_lo + r * S_STRIDE + c8 * 8) = vl;
        }
        // stage B: 64 rows x 64 cols, hi + lo
        #pragma unroll
        for (int it = 0; it < 2; it++) {
            int idx = tid + it * 256;          // 0..511
            int r = idx >> 3, c8 = idx & 7;
            size_t gi = (size_t)(block_n + r) * (K_TOT / 8) + (k0g >> 3) + c8;
            uint4 vh = ((const uint4*)g_Bhi)[gi];
            uint4 vl = ((const uint4*)g_Blo)[gi];
            *(uint4*)(Bs_hi + r * S_STRIDE + c8 * 8) = vh;
            *(uint4*)(Bs_lo + r * S_STRIDE + c8 * 8) = vl;
        }
        __syncthreads();

        #pragma unroll
        for (int ks = 0; ks < 4; ks++) {
            const int k0 = ks * 16;
            // A fragments (hi & lo) for 2 M-tiles
            uint32_t ah[2][4], al[2][4];
            #pragma unroll
            for (int mi = 0; mi < 2; mi++) {
                int r0 = warp_m * 32 + mi * 16 + g;
                const __nv_bfloat16* ph0 = As_hi + r0 * S_STRIDE + k0 + tg * 2;
                const __nv_bfloat16* ph1 = As_hi + (r0 + 8) * S_STRIDE + k0 + tg * 2;
                ah[mi][0] = *(const uint32_t*)ph0;
                ah[mi][1] = *(const uint32_t*)ph1;
                ah[mi][2] = *(const uint32_t*)(ph0 + 8);
                ah[mi][3] = *(const uint32_t*)(ph1 + 8);
                const __nv_bfloat16* pl0 = As_lo + r0 * S_STRIDE + k0 + tg * 2;
                const __nv_bfloat16* pl1 = As_lo + (r0 + 8) * S_STRIDE + k0 + tg * 2;
                al[mi][0] = *(const uint32_t*)pl0;
                al[mi][1] = *(const uint32_t*)pl1;
                al[mi][2] = *(const uint32_t*)(pl0 + 8);
                al[mi][3] = *(const uint32_t*)(pl1 + 8);
            }
            // B fragments (hi & lo) for 4 N-tiles
            uint32_t bh[4][2], bl[4][2];
            #pragma unroll
            for (int ni = 0; ni < 4; ni++) {
                int n0 = warp_n * 32 + ni * 8 + g;
                const __nv_bfloat16* qh = Bs_hi + n0 * S_STRIDE + k0 + tg * 2;
                bh[ni][0] = *(const uint32_t*)qh;
                bh[ni][1] = *(const uint32_t*)(qh + 8);
                const __nv_bfloat16* ql = Bs_lo + n0 * S_STRIDE + k0 + tg * 2;
                bl[ni][0] = *(const uint32_t*)ql;
                bl[ni][1] = *(const uint32_t*)(ql + 8);
            }
            // 3-term compensated MMAs
            #pragma unroll
            for (int mi = 0; mi < 2; mi++)
                #pragma unroll
                for (int ni = 0; ni < 4; ni++) {
                    mma16816(acc[mi][ni], ah[mi][0], ah[mi][1], ah[mi][2], ah[mi][3], bh[ni][0], bh[ni][1]);
                    mma16816(acc[mi][ni], ah[mi][0], ah[mi][1], ah[mi][2], ah[mi][3], bl[ni][0], bl[ni][1]);
                    mma16816(acc[mi][ni], al[mi][0], al[mi][1], al[mi][2], al[mi][3], bh[ni][0], bh[ni][1]);
                }
        }
        __syncthreads();
    }

    // epilogue: c0,c1 -> (row g), c2,c3 -> (row g+8), cols tg*2, tg*2+1
    #pragma unroll
    for (int mi = 0; mi < 2; mi++) {
        #pragma unroll
        for (int ni = 0; ni < 4; ni++) {
            int col = block_n + warp_n * 32 + ni * 8 + tg * 2;
            float bx = bias[col], by = bias[col + 1];
            int row0 = block_m + warp_m * 32 + mi * 16 + g;
            #pragma unroll
            for (int h = 0; h < 2; h++) {
                int row = row0 + h * 8;
                if (row < N_NODES) {
                    float vx = acc[mi][ni][h * 2 + 0] + bx;
                    float vy = acc[mi][ni][h * 2 + 1] + by;
                    if (RELU) { vx = fmaxf(vx, 0.f); vy = fmaxf(vy, 0.f); }
                    float2 o = {vx, vy};
                    *(float2*)&C[(size_t)row * DO + col] = o;
                }
            }
        }
    }
}

extern "C" void kernel_launch(void* const* d_in, const int* in_sizes, int n_in,
                              void* d_out, int out_size) {
    const float* x   = (const float*)d_in[0];
    const int*   ei  = (const int*)d_in[1];     // int32 (harness converts int64)
    const float* Wl0 = (const float*)d_in[2];
    const float* bl0 = (const float*)d_in[3];
    const float* Wr0 = (const float*)d_in[4];
    const float* Wl1 = (const float*)d_in[5];
    const float* bl1 = (const float*)d_in[6];
    const float* Wr1 = (const float*)d_in[7];
    const float* Wl2 = (const float*)d_in[8];
    const float* bl2 = (const float*)d_in[9];
    const float* Wr2 = (const float*)d_in[10];
    float* out = (float*)d_out;

    const int SMEM = 384 * S_STRIDE * 2;   // 55296 B (A 2x128 rows + B 2x64 rows, stride 72 bf16)
    cudaFuncSetAttribute(k_gemm_mma<128, true>,  cudaFuncAttributeMaxDynamicSharedMemorySize, SMEM);
    cudaFuncSetAttribute(k_gemm_mma<256, false>, cudaFuncAttributeMaxDynamicSharedMemorySize, SMEM);

    // --- CSR build (once, reused by all 3 layers) ---
    k_zero_deg<<<(N_NODES + 255) / 256, 256>>>();
    k_count<<<(E_EDGES + 255) / 256, 256>>>(ei);
    k_scan<<<1, 1024>>>();
    k_fill<<<(E_EDGES + 255) / 256, 256>>>(ei);

    const int GRID_M = (N_NODES + 127) / 128;   // 391

    // --- layer 0: x -> g_h0 (relu) ---
    k_prep_w<<<(128 * K_TOT + 255) / 256, 256>>>(Wl0, Wr0, 128);
    k_agg<<<(N_NODES + 7) / 8, 256>>>(x, 0);
    k_gemm_mma<128, true><<<dim3(GRID_M, 2), 256, SMEM>>>(bl0, nullptr, 0);

    // --- layer 1: g_h0 -> g_h1 (relu) ---
    k_prep_w<<<(128 * K_TOT + 255) / 256, 256>>>(Wl1, Wr1, 128);
    k_agg<<<(N_NODES + 7) / 8, 256>>>(nullptr, 1);
    k_gemm_mma<128, true><<<dim3(GRID_M, 2), 256, SMEM>>>(bl1, nullptr, 1);

    // --- layer 2: g_h1 -> out (no relu) ---
    k_prep_w<<<(256 * K_TOT + 255) / 256, 256>>>(Wl2, Wr2, 256);
    k_agg<<<(N_NODES + 7) / 8, 256>>>(nullptr, 2);
    k_gemm_mma<256, false><<<dim3(GRID_M, 4), 256, SMEM>>>(bl2, out, 2);
}

// round 11
// speedup vs baseline: 1.7074x; 1.0875x over previous
#include <cuda_runtime.h>
#include <cuda_bf16.h>
#include <cstdint>

#define N_NODES 50000
#define E_EDGES 800000
#define K_TOT   256     // concat K (mean 128 | self 128) for every layer

// ---------------- device scratch (no allocs allowed) ----------------
__device__ int   g_deg[N_NODES];
__device__ int   g_rowptr[N_NODES + 1];
__device__ int   g_cursor[N_NODES];
__device__ int   g_col[E_EDGES];
__device__ __align__(16) __nv_bfloat16 g_Ahi[(size_t)N_NODES * K_TOT];  // [N,256] hi split of [mean|h]
__device__ __align__(16) __nv_bfloat16 g_Alo[(size_t)N_NODES * K_TOT];  // [N,256] lo split
__device__ __align__(16) __nv_bfloat16 g_BhiA[3 * 256 * K_TOT];         // per-layer [Do,256] weight hi
__device__ __align__(16) __nv_bfloat16 g_BloA[3 * 256 * K_TOT];         // per-layer weight lo
__device__ __align__(16) float g_h0[(size_t)N_NODES * 128];
__device__ __align__(16) float g_h1[(size_t)N_NODES * 128];

// ---------------- helpers ----------------
__device__ __forceinline__ uint32_t smem_u32(const void* p) {
    uint32_t a;
    asm("{ .reg .u64 t; cvta.to.shared.u64 t, %1; cvt.u32.u64 %0, t; }" : "=r"(a) : "l"(p));
    return a;
}
__device__ __forceinline__ void cp16(void* sdst, const void* gsrc, int szr) {
    uint32_t d = smem_u32(sdst);
    asm volatile("cp.async.cg.shared.global [%0], [%1], 16, %2;" :: "r"(d), "l"(gsrc), "r"(szr) : "memory");
}
#define CP_COMMIT() asm volatile("cp.async.commit_group;" ::: "memory")
#define CP_WAIT1()  asm volatile("cp.async.wait_group 1;" ::: "memory")
#define CP_WAIT0()  asm volatile("cp.async.wait_group 0;" ::: "memory")

// ---------------- CSR build ----------------
__global__ void k_zero_deg() {
    int i = blockIdx.x * blockDim.x + threadIdx.x;
    if (i < N_NODES) g_deg[i] = 0;
}
__global__ void k_count(const int* __restrict__ ei) {
    int e = blockIdx.x * blockDim.x + threadIdx.x;
    if (e < E_EDGES) {
        int d = ei[E_EDGES + e];
        if (d >= 0 && d < N_NODES) atomicAdd(&g_deg[d], 1);
    }
}
__global__ void k_scan() {   // 1024 threads, shuffle-based block scan
    __shared__ int wsum[32];
    __shared__ int run_s;
    int t = threadIdx.x, lane = t & 31, wd = t >> 5;
    if (t == 0) run_s = 0;
    __syncthreads();
    for (int base = 0; base < N_NODES; base += 1024) {
        int i = base + t;
        int v = (i < N_NODES) ? g_deg[i] : 0;
        int s = v;
        #pragma unroll
        for (int o = 1; o < 32; o <<= 1) {
            int n = __shfl_up_sync(0xffffffffu, s, o);
            if (lane >= o) s += n;
        }
        if (lane == 31) wsum[wd] = s;
        __syncthreads();
        if (wd == 0) {
            int w = wsum[lane];
            #pragma unroll
            for (int o = 1; o < 32; o <<= 1) {
                int n = __shfl_up_sync(0xffffffffu, w, o);
                if (lane >= o) w += n;
            }
            wsum[lane] = w;
        }
        __syncthreads();
        int excl = run_s + (wd ? wsum[wd - 1] : 0) + s - v;
        if (i < N_NODES) { g_rowptr[i] = excl; g_cursor[i] = excl; }
        __syncthreads();
        if (t == 0) run_s += wsum[31];
        __syncthreads();
    }
    if (t == 0) g_rowptr[N_NODES] = run_s;
}
__global__ void k_fill(const int* __restrict__ ei) {
    int e = blockIdx.x * blockDim.x + threadIdx.x;
    if (e < E_EDGES) {
        int s = ei[e];
        int d = ei[E_EDGES + e];
        if (d >= 0 && d < N_NODES && s >= 0 && s < N_NODES) {
            int p = atomicAdd(&g_cursor[d], 1);
            g_col[p] = s;
        }
    }
}

// ---------------- weight prep, all 3 layers in one launch ----------------
__global__ void k_prep_all(const float* __restrict__ Wl0, const float* __restrict__ Wr0,
                           const float* __restrict__ Wl1, const float* __restrict__ Wr1,
                           const float* __restrict__ Wl2, const float* __restrict__ Wr2) {
    int idx = blockIdx.x * blockDim.x + threadIdx.x;     // over 3*65536
    if (idx >= 3 * 256 * K_TOT) return;
    int layer = idx >> 16;
    int rem = idx & 65535;
    int j = rem >> 8, k = rem & 255;
    int Do = (layer == 2) ? 256 : 128;
    if (j >= Do) return;
    const float* Wl = (layer == 0) ? Wl0 : (layer == 1) ? Wl1 : Wl2;
    const float* Wr = (layer == 0) ? Wr0 : (layer == 1) ? Wr1 : Wr2;
    float v = (k < 128) ? Wl[j * 128 + k] : Wr[j * 128 + (k - 128)];
    __nv_bfloat16 hi = __float2bfloat16_rn(v);
    float lo = v - __bfloat162float(hi);
    g_BhiA[idx] = hi;
    g_BloA[idx] = __float2bfloat16_rn(lo);
}

// ---------------- aggregation: warp/node gather-mean, emit hi/lo bf16 split ----------------
__device__ __forceinline__ void store_split(size_t off, float4 v) {
    __nv_bfloat16 h0 = __float2bfloat16_rn(v.x), h1 = __float2bfloat16_rn(v.y);
    __nv_bfloat16 h2 = __float2bfloat16_rn(v.z), h3 = __float2bfloat16_rn(v.w);
    __nv_bfloat162 a; a.x = h0; a.y = h1;
    __nv_bfloat162 b; b.x = h2; b.y = h3;
    *(__nv_bfloat162*)(g_Ahi + off)     = a;
    *(__nv_bfloat162*)(g_Ahi + off + 2) = b;
    __nv_bfloat162 la, lb;
    la.x = __float2bfloat16_rn(v.x - __bfloat162float(h0));
    la.y = __float2bfloat16_rn(v.y - __bfloat162float(h1));
    lb.x = __float2bfloat16_rn(v.z - __bfloat162float(h2));
    lb.y = __float2bfloat16_rn(v.w - __bfloat162float(h3));
    *(__nv_bfloat162*)(g_Alo + off)     = la;
    *(__nv_bfloat162*)(g_Alo + off + 2) = lb;
}

__global__ void k_agg(const float* __restrict__ x_ext, int sel) {
    const float* xin = (sel == 0) ? x_ext : (sel == 1) ? g_h0 : g_h1;
    int node = blockIdx.x * (blockDim.x >> 5) + (threadIdx.x >> 5);
    int lane = threadIdx.x & 31;
    if (node >= N_NODES) return;
    int beg = g_rowptr[node], end = g_rowptr[node + 1];
    const float4* x4 = (const float4*)xin;

    float4 a0 = {0.f, 0.f, 0.f, 0.f};
    float4 a1 = {0.f, 0.f, 0.f, 0.f};
    int e = beg;
    for (; e + 1 < end; e += 2) {
        int s0 = g_col[e], s1 = g_col[e + 1];
        float4 v0 = x4[(size_t)s0 * 32 + lane];
        float4 v1 = x4[(size_t)s1 * 32 + lane];
        a0.x += v0.x; a0.y += v0.y; a0.z += v0.z; a0.w += v0.w;
        a1.x += v1.x; a1.y += v1.y; a1.z += v1.z; a1.w += v1.w;
    }
    if (e < end) {
        int s0 = g_col[e];
        float4 v0 = x4[(size_t)s0 * 32 + lane];
        a0.x += v0.x; a0.y += v0.y; a0.z += v0.z; a0.w += v0.w;
    }
    int cnt = end - beg;
    float inv = 1.0f / (float)(cnt > 0 ? cnt : 1);
    float4 m;
    m.x = (a0.x + a1.x) * inv;
    m.y = (a0.y + a1.y) * inv;
    m.z = (a0.z + a1.z) * inv;
    m.w = (a0.w + a1.w) * inv;

    size_t base = (size_t)node * K_TOT + 4 * lane;
    store_split(base, m);                                   // cols 0..127: mean
    store_split(base + 128, x4[(size_t)node * 32 + lane]);  // cols 128..255: self
}

// ---------------- mma.sync bf16 helper ----------------
__device__ __forceinline__ void mma16816(float* c, uint32_t a0, uint32_t a1, uint32_t a2, uint32_t a3,
                                         uint32_t b0, uint32_t b1) {
    asm volatile("mma.sync.aligned.m16n8k16.row.col.f32.bf16.bf16.f32 "
                 "{%0,%1,%2,%3}, {%4,%5,%6,%7}, {%8,%9}, {%0,%1,%2,%3};"
                 : "+f"(c[0]), "+f"(c[1]), "+f"(c[2]), "+f"(c[3])
                 : "r"(a0), "r"(a1), "r"(a2), "r"(a3), "r"(b0), "r"(b1));
}

// ---------------- double-buffered tensor-core GEMM ----------------
// C[N,DO] = split([mean|h]) @ split(W)^T + bias (+relu)
// BM=128, BN=128, 512 threads: 16 warps as 4(M) x 4(N), warp tile 32x32.
// K staged in 4 chunks of 64 via cp.async, 2-deep pipeline.
// D += Ahi*Bhi + Ahi*Blo + Alo*Bhi  (fp32 accum in registers)
#define S_STRIDE 72                    // bf16 elems per SMEM row (144B)
#define BUF_ELEMS (4 * 128 * S_STRIDE) // As_hi, As_lo, Bs_hi, Bs_lo each 128 rows

template<int DO, bool RELU>
__global__ __launch_bounds__(512) void k_gemm_db(const float* __restrict__ bias,
                                                 float* __restrict__ Cext, int csel, int layer) {
    extern __shared__ __nv_bfloat16 sm[];
    float* C = (csel == 0) ? g_h0 : (csel == 1) ? g_h1 : Cext;
    const int tid = threadIdx.x;
    const int wid = tid >> 5, lane = tid & 31;
    const int warp_m = wid & 3, warp_n = wid >> 2;    // 4 x 4
    const int g = lane >> 2, tg = lane & 3;
    const int block_m = blockIdx.x * 128;
    const int block_n = blockIdx.y * 128;
    const size_t woff = (size_t)layer * 8192;         // layer offset in uint4 units (65536 bf16)

    // staging lambda: chunk ch -> buffer b (each thread: 8 cp.async of 16B)
    auto stage = [&](int ch, int b) {
        __nv_bfloat16* As_hi = sm + b * BUF_ELEMS;
        __nv_bfloat16* As_lo = As_hi + 128 * S_STRIDE;
        __nv_bfloat16* Bs_hi = As_lo + 128 * S_STRIDE;
        __nv_bfloat16* Bs_lo = Bs_hi + 128 * S_STRIDE;
        const int k8 = ch * 8;   // chunk k offset in uint4 units (64 bf16 = 8 uint4)
        #pragma unroll
        for (int it = 0; it < 2; it++) {
            int idx = tid + it * 512;          // 0..1023
            int r = idx >> 3, c8 = idx & 7;
            int row = block_m + r;
            int sz = (row < N_NODES) ? 16 : 0;
            int rowc = (row < N_NODES) ? row : (N_NODES - 1);
            size_t gi = (size_t)rowc * 32 + k8 + c8;
            cp16(As_hi + r * S_STRIDE + c8 * 8, (const char*)g_Ahi + gi * 16, sz);
            cp16(As_lo + r * S_STRIDE + c8 * 8, (const char*)g_Alo + gi * 16, sz);
        }
        #pragma unroll
        for (int it = 0; it < 2; it++) {
            int idx = tid + it * 512;
            int r = idx >> 3, c8 = idx & 7;
            size_t gi = woff + (size_t)(block_n + r) * 32 + k8 + c8;
            cp16(Bs_hi + r * S_STRIDE + c8 * 8, (const char*)g_BhiA + gi * 16, 16);
            cp16(Bs_lo + r * S_STRIDE + c8 * 8, (const char*)g_BloA + gi * 16, 16);
        }
        CP_COMMIT();
    };

    float acc[2][4][4];
    #pragma unroll
    for (int mi = 0; mi < 2; mi++)
        #pragma unroll
        for (int ni = 0; ni < 4; ni++)
            #pragma unroll
            for (int j = 0; j < 4; j++) acc[mi][ni][j] = 0.f;

    stage(0, 0);

    for (int ch = 0; ch < 4; ch++) {
        if (ch < 3) stage(ch + 1, (ch + 1) & 1);
        if (ch < 3) { CP_WAIT1(); } else { CP_WAIT0(); }
        __syncthreads();

        const __nv_bfloat16* base = sm + (ch & 1) * BUF_ELEMS;
        const __nv_bfloat16* As_hi = base;
        const __nv_bfloat16* As_lo = base + 128 * S_STRIDE;
        const __nv_bfloat16* Bs_hi = base + 256 * S_STRIDE;
        const __nv_bfloat16* Bs_lo = base + 384 * S_STRIDE;

        #pragma unroll
        for (int ks = 0; ks < 4; ks++) {
            const int k0 = ks * 16;
            uint32_t ah[2][4], al[2][4];
            #pragma unroll
            for (int mi = 0; mi < 2; mi++) {
                int r0 = warp_m * 32 + mi * 16 + g;
                const __nv_bfloat16* ph0 = As_hi + r0 * S_STRIDE + k0 + tg * 2;
                const __nv_bfloat16* ph1 = As_hi + (r0 + 8) * S_STRIDE + k0 + tg * 2;
                ah[mi][0] = *(const uint32_t*)ph0;
                ah[mi][1] = *(const uint32_t*)ph1;
                ah[mi][2] = *(const uint32_t*)(ph0 + 8);
                ah[mi][3] = *(const uint32_t*)(ph1 + 8);
                const __nv_bfloat16* pl0 = As_lo + r0 * S_STRIDE + k0 + tg * 2;
                const __nv_bfloat16* pl1 = As_lo + (r0 + 8) * S_STRIDE + k0 + tg * 2;
                al[mi][0] = *(const uint32_t*)pl0;
                al[mi][1] = *(const uint32_t*)pl1;
                al[mi][2] = *(const uint32_t*)(pl0 + 8);
                al[mi][3] = *(const uint32_t*)(pl1 + 8);
            }
            uint32_t bh[4][2], bl[4][2];
            #pragma unroll
            for (int ni = 0; ni < 4; ni++) {
                int n0 = warp_n * 32 + ni * 8 + g;
                const __nv_bfloat16* qh = Bs_hi + n0 * S_STRIDE + k0 + tg * 2;
                bh[ni][0] = *(const uint32_t*)qh;
                bh[ni][1] = *(const uint32_t*)(qh + 8);
                const __nv_bfloat16* ql = Bs_lo + n0 * S_STRIDE + k0 + tg * 2;
                bl[ni][0] = *(const uint32_t*)ql;
                bl[ni][1] = *(const uint32_t*)(ql + 8);
            }
            #pragma unroll
            for (int mi = 0; mi < 2; mi++)
                #pragma unroll
                for (int ni = 0; ni < 4; ni++) {
                    mma16816(acc[mi][ni], ah[mi][0], ah[mi][1], ah[mi][2], ah[mi][3], bh[ni][0], bh[ni][1]);
                    mma16816(acc[mi][ni], ah[mi][0], ah[mi][1], ah[mi][2], ah[mi][3], bl[ni][0], bl[ni][1]);
                    mma16816(acc[mi][ni], al[mi][0], al[mi][1], al[mi][2], al[mi][3], bh[ni][0], bh[ni][1]);
                }
        }
        __syncthreads();
    }

    // epilogue
    #pragma unroll
    for (int mi = 0; mi < 2; mi++) {
        #pragma unroll
        for (int ni = 0; ni < 4; ni++) {
            int col = block_n + warp_n * 32 + ni * 8 + tg * 2;
            float bx = bias[col], by = bias[col + 1];
            int row0 = block_m + warp_m * 32 + mi * 16 + g;
            #pragma unroll
            for (int h = 0; h < 2; h++) {
                int row = row0 + h * 8;
                if (row < N_NODES) {
                    float vx = acc[mi][ni][h * 2 + 0] + bx;
                    float vy = acc[mi][ni][h * 2 + 1] + by;
                    if (RELU) { vx = fmaxf(vx, 0.f); vy = fmaxf(vy, 0.f); }
                    float2 o = {vx, vy};
                    *(float2*)&C[(size_t)row * DO + col] = o;
                }
            }
        }
    }
}

extern "C" void kernel_launch(void* const* d_in, const int* in_sizes, int n_in,
                              void* d_out, int out_size) {
    const float* x   = (const float*)d_in[0];
    const int*   ei  = (const int*)d_in[1];     // int32 (harness converts int64)
    const float* Wl0 = (const float*)d_in[2];
    const float* bl0 = (const float*)d_in[3];
    const float* Wr0 = (const float*)d_in[4];
    const float* Wl1 = (const float*)d_in[5];
    const float* bl1 = (const float*)d_in[6];
    const float* Wr1 = (const float*)d_in[7];
    const float* Wl2 = (const float*)d_in[8];
    const float* bl2 = (const float*)d_in[9];
    const float* Wr2 = (const float*)d_in[10];
    float* out = (float*)d_out;

    const int SMEM = 2 * BUF_ELEMS * 2;   // 147456 B
    cudaFuncSetAttribute(k_gemm_db<128, true>,  cudaFuncAttributeMaxDynamicSharedMemorySize, SMEM);
    cudaFuncSetAttribute(k_gemm_db<256, false>, cudaFuncAttributeMaxDynamicSharedMemorySize, SMEM);

    // --- CSR build + weight prep (weights independent of everything else) ---
    k_zero_deg<<<(N_NODES + 255) / 256, 256>>>();
    k_count<<<(E_EDGES + 255) / 256, 256>>>(ei);
    k_prep_all<<<(3 * 256 * K_TOT + 255) / 256, 256>>>(Wl0, Wr0, Wl1, Wr1, Wl2, Wr2);
    k_scan<<<1, 1024>>>();
    k_fill<<<(E_EDGES + 255) / 256, 256>>>(ei);

    const int GRID_M = (N_NODES + 127) / 128;   // 391

    // --- layer 0: x -> g_h0 (relu) ---
    k_agg<<<(N_NODES + 7) / 8, 256>>>(x, 0);
    k_gemm_db<128, true><<<dim3(GRID_M, 1), 512, SMEM>>>(bl0, nullptr, 0, 0);

    // --- layer 1: g_h0 -> g_h1 (relu) ---
    k_agg<<<(N_NODES + 7) / 8, 256>>>(nullptr, 1);
    k_gemm_db<128, true><<<dim3(GRID_M, 1), 512, SMEM>>>(bl1, nullptr, 1, 1);

    // --- layer 2: g_h1 -> out (no relu) ---
    k_agg<<<(N_NODES + 7) / 8, 256>>>(nullptr, 2);
    k_gemm_db<256, false><<<dim3(GRID_M, 2), 512, SMEM>>>(bl2, out, 2, 2);
}

// round 13
// speedup vs baseline: 1.8616x; 1.0903x over previous
#include <cuda_runtime.h>
#include <cuda_bf16.h>
#include <cstdint>

#define N_NODES 50000
#define E_EDGES 800000
#define K_TOT   256     // concat K (mean 128 | self 128) for every layer
#define SCAN_BLOCKS ((N_NODES + 1023) / 1024)   // 49

// ---------------- device scratch (no allocs allowed) ----------------
__device__ int   g_deg[N_NODES];
__device__ int   g_rowptr[N_NODES + 1];
__device__ int   g_cursor[N_NODES];
__device__ int   g_col[E_EDGES];
__device__ int   g_bsum[SCAN_BLOCKS];
__device__ __align__(16) __nv_bfloat16 g_Ahi[(size_t)N_NODES * K_TOT];  // [N,256] hi split of [mean|h]
__device__ __align__(16) __nv_bfloat16 g_Alo[(size_t)N_NODES * K_TOT];  // [N,256] lo split
__device__ __align__(16) __nv_bfloat16 g_BhiA[3 * 256 * K_TOT];         // per-layer [Do,256] weight hi
__device__ __align__(16) __nv_bfloat16 g_BloA[3 * 256 * K_TOT];         // per-layer weight lo
__device__ __align__(16) float g_h0[(size_t)N_NODES * 128];
__device__ __align__(16) float g_h1[(size_t)N_NODES * 128];

// ---------------- helpers ----------------
__device__ __forceinline__ uint32_t smem_u32(const void* p) {
    uint32_t a;
    asm("{ .reg .u64 t; cvta.to.shared.u64 t, %1; cvt.u32.u64 %0, t; }" : "=r"(a) : "l"(p));
    return a;
}
__device__ __forceinline__ void cp16(void* sdst, const void* gsrc, int szr) {
    uint32_t d = smem_u32(sdst);
    asm volatile("cp.async.cg.shared.global [%0], [%1], 16, %2;" :: "r"(d), "l"(gsrc), "r"(szr) : "memory");
}
#define CP_COMMIT() asm volatile("cp.async.commit_group;" ::: "memory")
#define CP_WAIT1()  asm volatile("cp.async.wait_group 1;" ::: "memory")
#define CP_WAIT0()  asm volatile("cp.async.wait_group 0;" ::: "memory")

// ---------------- CSR build ----------------
__global__ void k_zero_deg() {
    int i = blockIdx.x * blockDim.x + threadIdx.x;
    if (i < N_NODES) g_deg[i] = 0;
}
__global__ void k_count(const int* __restrict__ ei) {
    int e = blockIdx.x * blockDim.x + threadIdx.x;
    if (e < E_EDGES) {
        int d = ei[E_EDGES + e];
        if (d >= 0 && d < N_NODES) atomicAdd(&g_deg[d], 1);
    }
}
// phase 1: each block scans its 1024-chunk (exclusive, local), writes block sum
__global__ void k_scan_part() {
    __shared__ int wsum[32];
    int t = threadIdx.x, lane = t & 31, wd = t >> 5;
    int i = blockIdx.x * 1024 + t;
    int v = (i < N_NODES) ? g_deg[i] : 0;
    int s = v;
    #pragma unroll
    for (int o = 1; o < 32; o <<= 1) {
        int n = __shfl_up_sync(0xffffffffu, s, o);
        if (lane >= o) s += n;
    }
    if (lane == 31) wsum[wd] = s;
    __syncthreads();
    if (wd == 0) {
        int w = wsum[lane];
        #pragma unroll
        for (int o = 1; o < 32; o <<= 1) {
            int n = __shfl_up_sync(0xffffffffu, w, o);
            if (lane >= o) w += n;
        }
        wsum[lane] = w;
    }
    __syncthreads();
    int excl_local = (wd ? wsum[wd - 1] : 0) + s - v;   // exclusive within block
    if (i < N_NODES) g_rowptr[i] = excl_local;
    if (t == 1023) g_bsum[blockIdx.x] = (wd ? wsum[wd - 1] : 0) + s;  // block total
}
// phase 2: add block-sum prefix; write cursor and rowptr[N]
__global__ void k_scan_add() {
    __shared__ int base_s;
    int t = threadIdx.x;
    if (t == 0) {
        int b = 0;
        #pragma unroll 1
        for (int j = 0; j < (int)blockIdx.x; j++) b += g_bsum[j];
        base_s = b;
    }
    __syncthreads();
    int i = blockIdx.x * 1024 + t;
    if (i < N_NODES) {
        int v = g_rowptr[i] + base_s;
        g_rowptr[i] = v;
        g_cursor[i] = v;
    }
    if (blockIdx.x == SCAN_BLOCKS - 1 && t == 0) {
        int tot = base_s + g_bsum[SCAN_BLOCKS - 1];
        g_rowptr[N_NODES] = tot;
    }
}
__global__ void k_fill(const int* __restrict__ ei) {
    int e = blockIdx.x * blockDim.x + threadIdx.x;
    if (e < E_EDGES) {
        int s = ei[e];
        int d = ei[E_EDGES + e];
        if (d >= 0 && d < N_NODES && s >= 0 && s < N_NODES) {
            int p = atomicAdd(&g_cursor[d], 1);
            g_col[p] = s;
        }
    }
}

// ---------------- weight prep, all 3 layers in one launch ----------------
__global__ void k_prep_all(const float* __restrict__ Wl0, const float* __restrict__ Wr0,
                           const float* __restrict__ Wl1, const float* __restrict__ Wr1,
                           const float* __restrict__ Wl2, const float* __restrict__ Wr2) {
    int idx = blockIdx.x * blockDim.x + threadIdx.x;     // over 3*65536
    if (idx >= 3 * 256 * K_TOT) return;
    int layer = idx >> 16;
    int rem = idx & 65535;
    int j = rem >> 8, k = rem & 255;
    int Do = (layer == 2) ? 256 : 128;
    if (j >= Do) return;
    const float* Wl = (layer == 0) ? Wl0 : (layer == 1) ? Wl1 : Wl2;
    const float* Wr = (layer == 0) ? Wr0 : (layer == 1) ? Wr1 : Wr2;
    float v = (k < 128) ? Wl[j * 128 + k] : Wr[j * 128 + (k - 128)];
    __nv_bfloat16 hi = __float2bfloat16_rn(v);
    float lo = v - __bfloat162float(hi);
    g_BhiA[idx] = hi;
    g_BloA[idx] = __float2bfloat16_rn(lo);
}

// ---------------- aggregation: warp/node gather-mean, emit hi/lo bf16 split ----------------
__device__ __forceinline__ void store_split(size_t off, float4 v) {
    __nv_bfloat16 h0 = __float2bfloat16_rn(v.x), h1 = __float2bfloat16_rn(v.y);
    __nv_bfloat16 h2 = __float2bfloat16_rn(v.z), h3 = __float2bfloat16_rn(v.w);
    __nv_bfloat162 a; a.x = h0; a.y = h1;
    __nv_bfloat162 b; b.x = h2; b.y = h3;
    *(__nv_bfloat162*)(g_Ahi + off)     = a;
    *(__nv_bfloat162*)(g_Ahi + off + 2) = b;
    __nv_bfloat162 la, lb;
    la.x = __float2bfloat16_rn(v.x - __bfloat162float(h0));
    la.y = __float2bfloat16_rn(v.y - __bfloat162float(h1));
    lb.x = __float2bfloat16_rn(v.z - __bfloat162float(h2));
    lb.y = __float2bfloat16_rn(v.w - __bfloat162float(h3));
    *(__nv_bfloat162*)(g_Alo + off)     = la;
    *(__nv_bfloat162*)(g_Alo + off + 2) = lb;
}

__global__ void k_agg(const float* __restrict__ x_ext, int sel) {
    const float* xin = (sel == 0) ? x_ext : (sel == 1) ? g_h0 : g_h1;
    int node = blockIdx.x * (blockDim.x >> 5) + (threadIdx.x >> 5);
    int lane = threadIdx.x & 31;
    if (node >= N_NODES) return;
    int beg = g_rowptr[node], end = g_rowptr[node + 1];
    const float4* x4 = (const float4*)xin;

    float4 a0 = {0.f, 0.f, 0.f, 0.f};
    float4 a1 = {0.f, 0.f, 0.f, 0.f};
    int e = beg;
    for (; e + 1 < end; e += 2) {
        int s0 = g_col[e], s1 = g_col[e + 1];
        float4 v0 = x4[(size_t)s0 * 32 + lane];
        float4 v1 = x4[(size_t)s1 * 32 + lane];
        a0.x += v0.x; a0.y += v0.y; a0.z += v0.z; a0.w += v0.w;
        a1.x += v1.x; a1.y += v1.y; a1.z += v1.z; a1.w += v1.w;
    }
    if (e < end) {
        int s0 = g_col[e];
        float4 v0 = x4[(size_t)s0 * 32 + lane];
        a0.x += v0.x; a0.y += v0.y; a0.z += v0.z; a0.w += v0.w;
    }
    int cnt = end - beg;
    float inv = 1.0f / (float)(cnt > 0 ? cnt : 1);
    float4 m;
    m.x = (a0.x + a1.x) * inv;
    m.y = (a0.y + a1.y) * inv;
    m.z = (a0.z + a1.z) * inv;
    m.w = (a0.w + a1.w) * inv;

    size_t base = (size_t)node * K_TOT + 4 * lane;
    store_split(base, m);                                   // cols 0..127: mean
    store_split(base + 128, x4[(size_t)node * 32 + lane]);  // cols 128..255: self
}

// ---------------- mma.sync bf16 helper ----------------
__device__ __forceinline__ void mma16816(float* c, uint32_t a0, uint32_t a1, uint32_t a2, uint32_t a3,
                                         uint32_t b0, uint32_t b1) {
    asm volatile("mma.sync.aligned.m16n8k16.row.col.f32.bf16.bf16.f32 "
                 "{%0,%1,%2,%3}, {%4,%5,%6,%7}, {%8,%9}, {%0,%1,%2,%3};"
                 : "+f"(c[0]), "+f"(c[1]), "+f"(c[2]), "+f"(c[3])
                 : "r"(a0), "r"(a1), "r"(a2), "r"(a3), "r"(b0), "r"(b1));
}

// ---------------- double-buffered tensor-core GEMM ----------------
// C[N,DO] = split([mean|h]) @ split(W)^T + bias (+relu)
// BM=128, BN=128, 512 threads: 16 warps as 4(M) x 4(N), warp tile 32x32.
// K staged in 4 chunks of 64 via cp.async, 2-deep pipeline.
// D += Ahi*Bhi + Ahi*Blo + Alo*Bhi  (fp32 accum in registers)
#define S_STRIDE 72                    // bf16 elems per SMEM row (144B)
#define BUF_ELEMS (4 * 128 * S_STRIDE) // As_hi, As_lo, Bs_hi, Bs_lo each 128 rows

template<int DO, bool RELU>
__global__ __launch_bounds__(512) void k_gemm_db(const float* __restrict__ bias,
                                                 float* __restrict__ Cext, int csel, int layer) {
    extern __shared__ __nv_bfloat16 sm[];
    float* C = (csel == 0) ? g_h0 : (csel == 1) ? g_h1 : Cext;
    const int tid = threadIdx.x;
    const int wid = tid >> 5, lane = tid & 31;
    const int warp_m = wid & 3, warp_n = wid >> 2;    // 4 x 4
    const int g = lane >> 2, tg = lane & 3;
    const int block_m = blockIdx.x * 128;
    const int block_n = blockIdx.y * 128;
    const size_t woff = (size_t)layer * 8192;         // layer offset in uint4 units (65536 bf16)

    // staging lambda: chunk ch -> buffer b (each thread: 8 cp.async of 16B)
    auto stage = [&](int ch, int b) {
        __nv_bfloat16* As_hi = sm + b * BUF_ELEMS;
        __nv_bfloat16* As_lo = As_hi + 128 * S_STRIDE;
        __nv_bfloat16* Bs_hi = As_lo + 128 * S_STRIDE;
        __nv_bfloat16* Bs_lo = Bs_hi + 128 * S_STRIDE;
        const int k8 = ch * 8;   // chunk k offset in uint4 units (64 bf16 = 8 uint4)
        #pragma unroll
        for (int it = 0; it < 2; it++) {
            int idx = tid + it * 512;          // 0..1023
            int r = idx >> 3, c8 = idx & 7;
            int row = block_m + r;
            int sz = (row < N_NODES) ? 16 : 0;
            int rowc = (row < N_NODES) ? row : (N_NODES - 1);
            size_t gi = (size_t)rowc * 32 + k8 + c8;
            cp16(As_hi + r * S_STRIDE + c8 * 8, (const char*)g_Ahi + gi * 16, sz);
            cp16(As_lo + r * S_STRIDE + c8 * 8, (const char*)g_Alo + gi * 16, sz);
        }
        #pragma unroll
        for (int it = 0; it < 2; it++) {
            int idx = tid + it * 512;
            int r = idx >> 3, c8 = idx & 7;
            size_t gi = woff + (size_t)(block_n + r) * 32 + k8 + c8;
            cp16(Bs_hi + r * S_STRIDE + c8 * 8, (const char*)g_BhiA + gi * 16, 16);
            cp16(Bs_lo + r * S_STRIDE + c8 * 8, (const char*)g_BloA + gi * 16, 16);
        }
        CP_COMMIT();
    };

    float acc[2][4][4];
    #pragma unroll
    for (int mi = 0; mi < 2; mi++)
        #pragma unroll
        for (int ni = 0; ni < 4; ni++)
            #pragma unroll
            for (int j = 0; j < 4; j++) acc[mi][ni][j] = 0.f;

    stage(0, 0);

    for (int ch = 0; ch < 4; ch++) {
        if (ch < 3) stage(ch + 1, (ch + 1) & 1);
        if (ch < 3) { CP_WAIT1(); } else { CP_WAIT0(); }
        __syncthreads();

        const __nv_bfloat16* base = sm + (ch & 1) * BUF_ELEMS;
        const __nv_bfloat16* As_hi = base;
        const __nv_bfloat16* As_lo = base + 128 * S_STRIDE;
        const __nv_bfloat16* Bs_hi = base + 256 * S_STRIDE;
        const __nv_bfloat16* Bs_lo = base + 384 * S_STRIDE;

        #pragma unroll
        for (int ks = 0; ks < 4; ks++) {
            const int k0 = ks * 16;
            uint32_t ah[2][4], al[2][4];
            #pragma unroll
            for (int mi = 0; mi < 2; mi++) {
                int r0 = warp_m * 32 + mi * 16 + g;
                const __nv_bfloat16* ph0 = As_hi + r0 * S_STRIDE + k0 + tg * 2;
                const __nv_bfloat16* ph1 = As_hi + (r0 + 8) * S_STRIDE + k0 + tg * 2;
                ah[mi][0] = *(const uint32_t*)ph0;
                ah[mi][1] = *(const uint32_t*)ph1;
                ah[mi][2] = *(const uint32_t*)(ph0 + 8);
                ah[mi][3] = *(const uint32_t*)(ph1 + 8);
                const __nv_bfloat16* pl0 = As_lo + r0 * S_STRIDE + k0 + tg * 2;
                const __nv_bfloat16* pl1 = As_lo + (r0 + 8) * S_STRIDE + k0 + tg * 2;
                al[mi][0] = *(const uint32_t*)pl0;
                al[mi][1] = *(const uint32_t*)pl1;
                al[mi][2] = *(const uint32_t*)(pl0 + 8);
                al[mi][3] = *(const uint32_t*)(pl1 + 8);
            }
            uint32_t bh[4][2], bl[4][2];
            #pragma unroll
            for (int ni = 0; ni < 4; ni++) {
                int n0 = warp_n * 32 + ni * 8 + g;
                const __nv_bfloat16* qh = Bs_hi + n0 * S_STRIDE + k0 + tg * 2;
                bh[ni][0] = *(const uint32_t*)qh;
                bh[ni][1] = *(const uint32_t*)(qh + 8);
                const __nv_bfloat16* ql = Bs_lo + n0 * S_STRIDE + k0 + tg * 2;
                bl[ni][0] = *(const uint32_t*)ql;
                bl[ni][1] = *(const uint32_t*)(ql + 8);
            }
            #pragma unroll
            for (int mi = 0; mi < 2; mi++)
                #pragma unroll
                for (int ni = 0; ni < 4; ni++) {
                    mma16816(acc[mi][ni], ah[mi][0], ah[mi][1], ah[mi][2], ah[mi][3], bh[ni][0], bh[ni][1]);
                    mma16816(acc[mi][ni], ah[mi][0], ah[mi][1], ah[mi][2], ah[mi][3], bl[ni][0], bl[ni][1]);
                    mma16816(acc[mi][ni], al[mi][0], al[mi][1], al[mi][2], al[mi][3], bh[ni][0], bh[ni][1]);
                }
        }
        __syncthreads();
    }

    // epilogue
    #pragma unroll
    for (int mi = 0; mi < 2; mi++) {
        #pragma unroll
        for (int ni = 0; ni < 4; ni++) {
            int col = block_n + warp_n * 32 + ni * 8 + tg * 2;
            float bx = bias[col], by = bias[col + 1];
            int row0 = block_m + warp_m * 32 + mi * 16 + g;
            #pragma unroll
            for (int h = 0; h < 2; h++) {
                int row = row0 + h * 8;
                if (row < N_NODES) {
                    float vx = acc[mi][ni][h * 2 + 0] + bx;
                    float vy = acc[mi][ni][h * 2 + 1] + by;
                    if (RELU) { vx = fmaxf(vx, 0.f); vy = fmaxf(vy, 0.f); }
                    float2 o = {vx, vy};
                    *(float2*)&C[(size_t)row * DO + col] = o;
                }
            }
        }
    }
}

extern "C" void kernel_launch(void* const* d_in, const int* in_sizes, int n_in,
                              void* d_out, int out_size) {
    const float* x   = (const float*)d_in[0];
    const int*   ei  = (const int*)d_in[1];     // int32 (harness converts int64)
    const float* Wl0 = (const float*)d_in[2];
    const float* bl0 = (const float*)d_in[3];
    const float* Wr0 = (const float*)d_in[4];
    const float* Wl1 = (const float*)d_in[5];
    const float* bl1 = (const float*)d_in[6];
    const float* Wr1 = (const float*)d_in[7];
    const float* Wl2 = (const float*)d_in[8];
    const float* bl2 = (const float*)d_in[9];
    const float* Wr2 = (const float*)d_in[10];
    float* out = (float*)d_out;

    const int SMEM = 2 * BUF_ELEMS * 2;   // 147456 B
    cudaFuncSetAttribute(k_gemm_db<128, true>,  cudaFuncAttributeMaxDynamicSharedMemorySize, SMEM);
    cudaFuncSetAttribute(k_gemm_db<256, false>, cudaFuncAttributeMaxDynamicSharedMemorySize, SMEM);

    // --- CSR build + weight prep (weights independent of everything else) ---
    k_zero_deg<<<(N_NODES + 255) / 256, 256>>>();
    k_count<<<(E_EDGES + 255) / 256, 256>>>(ei);
    k_prep_all<<<(3 * 256 * K_TOT + 255) / 256, 256>>>(Wl0, Wr0, Wl1, Wr1, Wl2, Wr2);
    k_scan_part<<<SCAN_BLOCKS, 1024>>>();
    k_scan_add<<<SCAN_BLOCKS, 1024>>>();
    k_fill<<<(E_EDGES + 255) / 256, 256>>>(ei);

    const int GRID_M = (N_NODES + 127) / 128;   // 391

    // --- layer 0: x -> g_h0 (relu) ---
    k_agg<<<(N_NODES + 7) / 8, 256>>>(x, 0);
    k_gemm_db<128, true><<<dim3(GRID_M, 1), 512, SMEM>>>(bl0, nullptr, 0, 0);

    // --- layer 1: g_h0 -> g_h1 (relu) ---
    k_agg<<<(N_NODES + 7) / 8, 256>>>(nullptr, 1);
    k_gemm_db<128, true><<<dim3(GRID_M, 1), 512, SMEM>>>(bl1, nullptr, 1, 1);

    // --- layer 2: g_h1 -> out (no relu) ---
    k_agg<<<(N_NODES + 7) / 8, 256>>>(nullptr, 2);
    k_gemm_db<256, false><<<dim3(GRID_M, 2), 512, SMEM>>>(bl2, out, 2, 2);
}